// round 10
// baseline (speedup 1.0000x reference)
#include <cuda_runtime.h>
#include <cuda_bf16.h>
#include <cstdint>

// out[b,s,e] = W_emb[e, tokens[b,s]] + W_pos[s,e]
// tokens: int32 (B,S)=(8,2048), W_emb: fp32 (E,V)=(512,50257),
// W_pos: fp32 (S,E)=(2048,512), out: fp32 (B,S,E)
//
// R9: 2 graph nodes total. Small kernels cost ~4-5us each in node overhead
// (measured: R6 scatter 4.96us for ~1us of work), so the bucket scatter is
// fused into the gather kernel as a prologue executed by blocks (y==0,x<64),
// with a device-wide spin barrier (done counter) before the gather phase.
// Deadlock-safe: 8 blocks/SM -> wave 1 = first ~1184 linear block IDs, which
// contains all 64 scatter blocks. Node 1 = memset of counters (394 words).

static constexpr int B = 8, S = 2048, E = 512, V = 50257;
static constexpr int BS = B * S;                 // 16384
static constexpr int BSHIFT = 7;                 // 128 vocab slots per bucket
static constexpr int NBUCK = (V >> BSHIFT) + 1;  // 393
static constexpr int CAP = 128;                  // slot stride per bucket
static constexpr int WPB_L = 3;                  // windows launched (96 >> max fill ~70)
static constexpr int NSCAT = BS / 256;           // 64 scatter blocks
static constexpr int ECH = 128;                  // e per chunk
static constexpr int NCH = E / ECH;              // 4 chunks (blockIdx.y)
static constexpr int ROWP = ECH + 5;             // 133: (5*lane)%32 conflict-free

// scratch (allocation-free rule: __device__ globals)
// g_meta[0..NBUCK) = bucket counters, g_meta[NBUCK] = scatter-done counter
__device__ unsigned int g_meta[NBUCK + 1];
__device__ unsigned int g_slots[NBUCK * CAP];    // (tok << 14) | bs

__global__ __launch_bounds__(256)
void mega_kernel(const int* __restrict__ tokens,
                 const float* __restrict__ W_emb,
                 const float* __restrict__ W_pos,
                 float* __restrict__ out)
{
    __shared__ float tile[32 * ROWP];            // 17,024 B
    __shared__ unsigned int s_ent[32];

    int tid  = threadIdx.x;

    // ---- phase 0: bucket scatter (blocks y==0, x<64 — all in wave 1) ----
    if (blockIdx.y == 0 && blockIdx.x < NSCAT) {
        int i = blockIdx.x * 256 + tid;          // [0, 16384)
        int t = __ldg(tokens + i);
        int b = t >> BSHIFT;
        unsigned int p = atomicAdd(&g_meta[b], 1u);
        // slot order within a bucket is nondeterministic, but every entry
        // writes only its own output rows -> final output is deterministic
        g_slots[b * CAP + p] = ((unsigned int)t << 14) | (unsigned int)i;
        __threadfence();                         // release this thread's stores
        __syncthreads();
        if (tid == 0)
            atomicAdd(&g_meta[NBUCK], 1u);       // signal this block done
    }

    // ---- spin barrier: wait for all 64 scatter blocks ----
    if (tid == 0) {
        while (*(volatile unsigned int*)&g_meta[NBUCK] < (unsigned)NSCAT)
            __nanosleep(32);
    }
    __syncthreads();
    __threadfence();                             // acquire before L2 reads

    // ---- phase 1: bucketed transposed gather ----
    int lane = tid & 31;
    int w    = tid >> 5;                         // warp id 0..7
    int bkt  = blockIdx.x / WPB_L;               // bucket
    int win  = blockIdx.x % WPB_L;               // 32-slot window within bucket
    int e0   = blockIdx.y * ECH;                 // e-chunk slowest in launch order

    if (bkt >= NBUCK) return;
    int cnt = (int)__ldcg(&g_meta[bkt]);         // L2 read (coherent)
    int cnt_w = cnt - win * 32;
    if (cnt_w <= 0) return;                      // uniform early-exit
    if (cnt_w > 32) cnt_w = 32;

    if (tid < 32 && tid < cnt_w)
        s_ent[tid] = __ldcg(&g_slots[bkt * CAP + win * 32 + tid]);
    __syncthreads();

    // gather: active lanes = bucketed tokens (span <=512 B -> ~4-5 lines per
    // warp-LDG). Warp w covers e_local [w*16, w*16+16). MLP=16.
    if (lane < cnt_w) {
        int tok = (int)(s_ent[lane] >> 14);
        const float* colbase = W_emb + (size_t)e0 * V + tok;
        #pragma unroll
        for (int i = 0; i < 16; i++) {
            int el = w * 16 + i;
            // STS banks (5*lane + el)%32 -> all distinct, conflict-free
            tile[lane * ROWP + el] = __ldg(colbase + (size_t)el * V);
        }
    }
    __syncthreads();

    // store: warp lanes span 32 consecutive e -> conflict-free LDS,
    // coalesced W_pos load (L2-resident) and coalesced output store.
    {
        int e_lo = tid & 127;
        int tsub = tid >> 7;                     // 0..1
        #pragma unroll
        for (int p = 0; p < 16; p++) {
            int row = p * 2 + tsub;
            if (row < cnt_w) {                   // uniform per 128-thread group
                unsigned int ent = s_ent[row];   // broadcast LDS
                int bs = (int)(ent & 16383u);
                int s  = bs & (S - 1);
                float v = tile[row * ROWP + e_lo]
                        + __ldg(W_pos + (size_t)s * E + e0 + e_lo);
                // streaming store: write-once output must not evict gather
                // sectors from L2
                __stcs(out + (size_t)bs * E + e0 + e_lo, v);
            }
        }
    }
}

// ---------------- launch: 2 graph nodes ----------------

extern "C" void kernel_launch(void* const* d_in, const int* in_sizes, int n_in,
                              void* d_out, int out_size)
{
    const int*   tokens = (const int*)d_in[0];
    const float* W_emb  = (const float*)d_in[1];
    const float* W_pos  = (const float*)d_in[2];
    float*       out    = (float*)d_out;

    // node 1: zero bucket counters + done counter (394 words)
    void* meta_ptr = nullptr;
    cudaGetSymbolAddress(&meta_ptr, g_meta);
    cudaMemsetAsync(meta_ptr, 0, (NBUCK + 1) * sizeof(unsigned int));

    // node 2: fused scatter + barrier + gather
    dim3 grid(NBUCK * WPB_L, NCH);               // (1179, 4)
    mega_kernel<<<grid, 256>>>(tokens, W_emb, W_pos, out);
}

// round 11
// speedup vs baseline: 1.1727x; 1.1727x over previous
#include <cuda_runtime.h>
#include <cuda_bf16.h>
#include <cstdint>

// out[b,s,e] = W_emb[e, tokens[b,s]] + W_pos[s,e]
// tokens: int32 (B,S)=(8,2048), W_emb: fp32 (E,V)=(512,50257),
// W_pos: fp32 (S,E)=(2048,512), out: fp32 (B,S,E)
//
// R10: 3 nodes (memset + scatter + gather).
//  - scatter: fixed-capacity buckets (tok>>7, CAP=128) — no hist, no scan.
//  - gather: each block redundantly prefix-scans the 393 bucket counts in
//    smem (~700 cyc) and processes EXACTLY 32 compact entries via binary
//    search -> 100% lane utilization, grid (512,4), no partial windows.
//  - gather inner loop register-batched: 16 independent LDGs in flight
//    before any STS (the 23.6us version was MLP-limited: DRAM only 61%
//    with nothing else saturated).

static constexpr int B = 8, S = 2048, E = 512, V = 50257;
static constexpr int BS = B * S;                 // 16384
static constexpr int BSHIFT = 7;                 // 128 vocab slots per bucket
static constexpr int NBUCK = (V >> BSHIFT) + 1;  // 393
static constexpr int CAP = 128;                  // slot stride (max fill ~70)
static constexpr int ECH = 128;                  // e per chunk
static constexpr int NCH = E / ECH;              // 4 chunks (blockIdx.y)
static constexpr int ROWP = ECH + 5;             // 133: (5*lane)%32 conflict-free

// scratch (allocation-free rule: __device__ globals)
__device__ unsigned int g_cnt[NBUCK];            // zeroed by memset node
__device__ unsigned int g_slots[NBUCK * CAP];    // (tok << 14) | bs

// ---------------- node 2: bucket scatter (the entire "sort") --------------

__global__ void scatter_kernel(const int* __restrict__ tokens)
{
    int i = blockIdx.x * blockDim.x + threadIdx.x;
    if (i < BS) {
        int t = tokens[i];
        int b = t >> BSHIFT;
        unsigned int p = atomicAdd(&g_cnt[b], 1u);   // L2 atomic, ~42/bucket
        // slot order within a bucket is nondeterministic, but every entry
        // writes only its own output rows -> final output is deterministic
        g_slots[b * CAP + p] = ((unsigned int)t << 14) | (unsigned int)i;
    }
}

// ---------------- node 3: compact transposed gather ----------------

__global__ __launch_bounds__(256)
void gather_compact_kernel(const float* __restrict__ W_emb,
                           const float* __restrict__ W_pos,
                           float* __restrict__ out)
{
    __shared__ float tile[32 * ROWP];            // 17,024 B
    __shared__ unsigned int s_pref[512];         // bucket-start prefix sums
    __shared__ unsigned int ssum[256];
    __shared__ unsigned int s_ent[32];

    int tid  = threadIdx.x;
    int lane = tid & 31;
    int w    = tid >> 5;                         // warp id 0..7
    int e0   = blockIdx.y * ECH;                 // e-chunk slowest in launch order

    // ---- redundant in-block scan of bucket counts (~700 cyc) ----
    int b0 = tid * 2, b1 = tid * 2 + 1;
    unsigned int c0 = (b0 < NBUCK) ? __ldg(&g_cnt[b0]) : 0u;
    unsigned int c1 = (b1 < NBUCK) ? __ldg(&g_cnt[b1]) : 0u;
    ssum[tid] = c0 + c1;
    __syncthreads();
    #pragma unroll
    for (int off = 1; off < 256; off <<= 1) {    // Hillis-Steele, 8 rounds
        unsigned int v = (tid >= off) ? ssum[tid - off] : 0u;
        __syncthreads();
        ssum[tid] += v;
        __syncthreads();
    }
    unsigned int ex = (tid > 0) ? ssum[tid - 1] : 0u;
    s_pref[b0] = ex;                             // bins >= NBUCK get total=16384
    s_pref[b1] = ex + c0;
    __syncthreads();

    // ---- this block's 32 compact entries via binary search ----
    if (tid < 32) {
        unsigned int id = blockIdx.x * 32 + tid; // [0, 16384), always valid
        int lo = 0;
        #pragma unroll
        for (int st = 256; st >= 1; st >>= 1)    // largest lo: s_pref[lo] <= id
            if (s_pref[lo + st] <= id) lo += st;
        s_ent[tid] = __ldg(&g_slots[lo * CAP + (id - s_pref[lo])]);
    }
    __syncthreads();

    // ---- gather: 16 independent LDGs batched into registers, then STS ----
    // lanes = 32 bucketed tokens (span <=512 B -> ~4-5 lines per warp-LDG)
    {
        int tok = (int)(s_ent[lane] >> 14);
        const float* base = W_emb + ((size_t)e0 + (size_t)(w * 16)) * V + tok;
        float r[16];
        #pragma unroll
        for (int i = 0; i < 16; i++)
            r[i] = __ldg(base + (size_t)i * V);  // all in flight before STS
        #pragma unroll
        for (int i = 0; i < 16; i++)
            tile[lane * ROWP + w * 16 + i] = r[i];  // banks (5*lane+el)%32, clean
    }
    __syncthreads();

    // ---- store: conflict-free LDS, coalesced W_pos + output ----
    {
        int e_lo = tid & 127;
        int tsub = tid >> 7;                     // 0..1
        #pragma unroll
        for (int p = 0; p < 16; p++) {
            int row = p * 2 + tsub;              // all 32 rows valid (compact)
            unsigned int ent = s_ent[row];       // broadcast LDS
            int bs = (int)(ent & 16383u);
            int s  = bs & (S - 1);
            float v = tile[row * ROWP + e_lo]
                    + __ldg(W_pos + (size_t)s * E + e0 + e_lo);
            // streaming store: write-once output must not evict gather sectors
            __stcs(out + (size_t)bs * E + e0 + e_lo, v);
        }
    }
}

// ---------------- launch: 3 graph nodes ----------------

extern "C" void kernel_launch(void* const* d_in, const int* in_sizes, int n_in,
                              void* d_out, int out_size)
{
    const int*   tokens = (const int*)d_in[0];
    const float* W_emb  = (const float*)d_in[1];
    const float* W_pos  = (const float*)d_in[2];
    float*       out    = (float*)d_out;

    // node 1: zero bucket counters (1.6 KB)
    void* cnt_ptr = nullptr;
    cudaGetSymbolAddress(&cnt_ptr, g_cnt);
    cudaMemsetAsync(cnt_ptr, 0, NBUCK * sizeof(unsigned int));

    // node 2: bucket scatter
    scatter_kernel<<<BS / 256, 256>>>(tokens);

    // node 3: compact gather, grid (512, 4) — e-chunk slowest
    dim3 grid(BS / 32, NCH);
    gather_compact_kernel<<<grid, 256>>>(W_emb, W_pos, out);
}

// round 12
// speedup vs baseline: 1.2189x; 1.0393x over previous
#include <cuda_runtime.h>
#include <cuda_bf16.h>
#include <cstdint>

// out[b,s,e] = W_emb[e, tokens[b,s]] + W_pos[s,e]
// tokens: int32 (B,S)=(8,2048), W_emb: fp32 (E,V)=(512,50257),
// W_pos: fp32 (S,E)=(2048,512), out: fp32 (B,S,E)
//
// R11: 3 nodes (memset + scatter + gather).
//  - scatter: fixed-capacity buckets (tok>>7, CAP=128), and its LAST block
//    (fence+ticket) warp-scans the 393 counts ONCE into g_pref[512]
//    (sentinel 16384 above NBUCK). R10's mistake — every gather block
//    redoing this scan (16 syncs + 394 global words) — is gone.
//  - gather: cheap prologue (coalesced 512-word prefix load + 9-step binary
//    search for 32 threads), 100% compact lanes, grid (512,4), and the
//    16-deep register-batched gather burst for max MLP.

static constexpr int B = 8, S = 2048, E = 512, V = 50257;
static constexpr int BS = B * S;                 // 16384
static constexpr int BSHIFT = 7;                 // 128 vocab slots per bucket
static constexpr int NBUCK = (V >> BSHIFT) + 1;  // 393
static constexpr int CAP = 128;                  // slot stride (max fill ~70)
static constexpr int NSCAT = BS / 256;           // 64 scatter blocks
static constexpr int ECH = 128;                  // e per chunk
static constexpr int NCH = E / ECH;              // 4 chunks (blockIdx.y)
static constexpr int ROWP = ECH + 5;             // 133: (5*lane)%32 conflict-free

// scratch (allocation-free rule: __device__ globals)
// g_meta[0..NBUCK) = bucket counters, g_meta[NBUCK] = done ticket (memset 0)
__device__ unsigned int g_meta[NBUCK + 1];
__device__ unsigned int g_pref[512];             // bucket-start prefix + sentinels
__device__ unsigned int g_slots[NBUCK * CAP];    // (tok << 14) | bs

// ---------- node 2: bucket scatter + last-block prefix scan ----------

__global__ __launch_bounds__(256)
void scatter_kernel(const int* __restrict__ tokens)
{
    __shared__ bool s_last;
    int tid = threadIdx.x;
    int i = blockIdx.x * 256 + tid;              // [0, 16384)

    int t = __ldg(tokens + i);
    int b = t >> BSHIFT;
    unsigned int p = atomicAdd(&g_meta[b], 1u);  // L2 atomic, ~42/bucket total
    // slot order within a bucket is nondeterministic, but every entry writes
    // only its own output rows -> final output is deterministic
    g_slots[b * CAP + p] = ((unsigned int)t << 14) | (unsigned int)i;

    __threadfence();                             // release slot stores
    __syncthreads();
    if (tid == 0)
        s_last = (atomicAdd(&g_meta[NBUCK], 1u) == (unsigned)(NSCAT - 1));
    __syncthreads();

    // last block: warp-scan 393 counts -> exclusive prefix, sentinels = BS
    if (s_last && tid < 32) {
        unsigned int run = 0;
        #pragma unroll
        for (int base = 0; base < 512; base += 32) {
            int idx = base + tid;
            unsigned int c = (idx < NBUCK) ? __ldcg(&g_meta[idx]) : 0u;
            unsigned int inc = c;
            #pragma unroll
            for (int off = 1; off < 32; off <<= 1) {
                unsigned int v = __shfl_up_sync(0xffffffffu, inc, off);
                if (tid >= off) inc += v;
            }
            g_pref[idx] = run + inc - c;         // exclusive prefix
            run += __shfl_sync(0xffffffffu, inc, 31);
        }
    }
}

// ---------- node 3: compact transposed gather ----------

__global__ __launch_bounds__(256)
void gather_compact_kernel(const float* __restrict__ W_emb,
                           const float* __restrict__ W_pos,
                           float* __restrict__ out)
{
    __shared__ float tile[32 * ROWP];            // 17,024 B
    __shared__ unsigned int s_pref[512];
    __shared__ unsigned int s_ent[32];

    int tid  = threadIdx.x;
    int lane = tid & 31;
    int w    = tid >> 5;                         // warp id 0..7
    int e0   = blockIdx.y * ECH;                 // e-chunk slowest in launch order

    // cheap prologue: coalesced prefix load (L2-hot, 2 KB), one sync
    s_pref[tid]       = __ldg(&g_pref[tid]);
    s_pref[tid + 256] = __ldg(&g_pref[tid + 256]);
    __syncthreads();

    // this block's 32 compact entries via binary search (9 dependent LDS)
    if (tid < 32) {
        unsigned int id = blockIdx.x * 32 + tid; // [0, 16384), always valid
        int lo = 0;
        #pragma unroll
        for (int st = 256; st >= 1; st >>= 1)    // largest lo: s_pref[lo] <= id
            if (s_pref[lo + st] <= id) lo += st;
        s_ent[tid] = __ldg(&g_slots[lo * CAP + (id - s_pref[lo])]);
    }
    __syncthreads();

    // gather: 16 independent LDGs batched into registers, then STS.
    // lanes = 32 bucketed tokens (span <=512 B -> ~4-5 lines per warp-LDG)
    {
        int tok = (int)(s_ent[lane] >> 14);
        const float* base = W_emb + ((size_t)e0 + (size_t)(w * 16)) * V + tok;
        float r[16];
        #pragma unroll
        for (int i = 0; i < 16; i++)
            r[i] = __ldg(base + (size_t)i * V);  // all in flight before STS
        #pragma unroll
        for (int i = 0; i < 16; i++)
            tile[lane * ROWP + w * 16 + i] = r[i];  // banks (5*lane+el)%32, clean
    }
    __syncthreads();

    // store: conflict-free LDS, coalesced W_pos (L2-resident) + output
    {
        int e_lo = tid & 127;
        int tsub = tid >> 7;                     // 0..1
        #pragma unroll
        for (int p = 0; p < 16; p++) {
            int row = p * 2 + tsub;              // all 32 rows valid (compact)
            unsigned int ent = s_ent[row];       // broadcast LDS
            int bs = (int)(ent & 16383u);
            int s  = bs & (S - 1);
            float v = tile[row * ROWP + e_lo]
                    + __ldg(W_pos + (size_t)s * E + e0 + e_lo);
            // streaming store: write-once output must not evict gather sectors
            __stcs(out + (size_t)bs * E + e0 + e_lo, v);
        }
    }
}

// ---------------- launch: 3 graph nodes ----------------

extern "C" void kernel_launch(void* const* d_in, const int* in_sizes, int n_in,
                              void* d_out, int out_size)
{
    const int*   tokens = (const int*)d_in[0];
    const float* W_emb  = (const float*)d_in[1];
    const float* W_pos  = (const float*)d_in[2];
    float*       out    = (float*)d_out;

    // node 1: zero bucket counters + done ticket (1.6 KB)
    void* meta_ptr = nullptr;
    cudaGetSymbolAddress(&meta_ptr, g_meta);
    cudaMemsetAsync(meta_ptr, 0, (NBUCK + 1) * sizeof(unsigned int));

    // node 2: scatter (+ last-block scan)
    scatter_kernel<<<NSCAT, 256>>>(tokens);

    // node 3: compact gather, grid (512, 4) — e-chunk slowest
    dim3 grid(BS / 32, NCH);
    gather_compact_kernel<<<grid, 256>>>(W_emb, W_pos, out);
}